// round 3
// baseline (speedup 1.0000x reference)
#include <cuda_runtime.h>
#include <cuda_bf16.h>
#include <stdint.h>

#define NB   32
#define MCH  16          // merged channels = Dp*C = 2*8
#define HP   128
#define WPD  128
#define HO   126
#define WO   126
#define LTOT (HO*WO)     // 15876
#define OD   128
#define PD   144
#define WSTRIDE 168      // padded W row stride (halves), conflict-free A loads
#define CENTER 2.7416f   // E[chi_8] analytic mean of pooled values

#define TILE_L 128
#define NTILES 125       // ceil(15876/128)

// ---------------- device scratch (static, no allocation) ----------------
__device__ __align__(16) __nv_bfloat16 g_pooled[NB*MCH*HP*WPD]; // centered bf16
__device__ __align__(16) __nv_bfloat16 g_w2[OD*WSTRIDE];        // reordered W, padded rows
__device__ float g_const2[OD];                                   // b + M * sum_k W
__device__ float g_acc[NB*OD];                                   // per (n,o) celu sums

// ---------------- prep: reorder W to (shift, channel) K-order, fold bias ----------------
__global__ void prep_kernel(const float* __restrict__ w, const float* __restrict__ b) {
    int tid = threadIdx.x;
    for (int i = tid; i < NB*OD; i += blockDim.x) g_acc[i] = 0.f;
    if (tid < OD) {
        int o = tid;
        float s = 0.f;
        #pragma unroll 4
        for (int k = 0; k < PD; k++) s += w[o*PD + k];
        g_const2[o] = b[o] + CENTER * s;
        for (int kp = 0; kp < PD; kp++) {
            int c   = kp & 15;     // merged channel
            int sft = kp >> 4;     // 0..8 = ki*3+kj
            g_w2[o*WSTRIDE + kp] = __float2bfloat16(w[o*PD + c*9 + sft]);
        }
    }
}

// ---------------- pass 1: LPPool3d + depth-merge + center + bf16 ----------------
__global__ void pool_kernel(const float* __restrict__ x) {
    int idx = blockIdx.x * 256 + threadIdx.x;       // over 32*16*128*128
    int n   = idx >> 18;
    int rem = idx & 262143;
    int mc  = rem >> 14;                            // dp*8 + c
    int dp  = mc >> 3;
    int c   = mc & 7;
    int hw  = rem & 16383;
    int hp  = hw >> 7;
    int wp  = hw & 127;

    const float* base = x + ((((n*8 + c)*4 + 2*dp) * 256 + 2*hp) * 256 + 2*wp);
    float s = 0.f;
    #pragma unroll
    for (int dd = 0; dd < 2; dd++)
        #pragma unroll
        for (int hh = 0; hh < 2; hh++) {
            float2 v = *(const float2*)(base + dd*65536 + hh*256);
            s += v.x*v.x + v.y*v.y;
        }
    g_pooled[idx] = __float2bfloat16(sqrtf(s) - CENTER);
}

// ---------------- pass 2: implicit-conv GEMM (bf16 mma.sync) + CELU + sum ----------------
__device__ __forceinline__ void mma16816(float* c, const uint32_t* a, uint32_t b0, uint32_t b1) {
    asm volatile(
        "mma.sync.aligned.m16n8k16.row.col.f32.bf16.bf16.f32 "
        "{%0,%1,%2,%3}, {%4,%5,%6,%7}, {%8,%9}, {%0,%1,%2,%3};\n"
        : "+f"(c[0]), "+f"(c[1]), "+f"(c[2]), "+f"(c[3])
        : "r"(a[0]), "r"(a[1]), "r"(a[2]), "r"(a[3]), "r"(b0), "r"(b1));
}

// smem layout (bytes):
//   sW  [128][168] bf16 @ 0       (43008)
//   sM  [16][4][128] bf16 @ 43008 (16384)
//   sB  [128][18] bf16   @ 59392  ( 4608)
//   sC  [128] f32        @ 64000  (  512)
//   sDi [128] u8         @ 64512
//   sJj [128] u8         @ 64640   -> total 64768
#define SMEM_BYTES 64768

__global__ void gemm_kernel() {
    extern __shared__ __align__(16) unsigned char smem[];
    __nv_bfloat16* sW = (__nv_bfloat16*)(smem);
    __nv_bfloat16* sM = (__nv_bfloat16*)(smem + 43008);
    __nv_bfloat16* sB = (__nv_bfloat16*)(smem + 59392);
    float*         sC = (float*)(smem + 64000);
    unsigned char* sDi = smem + 64512;
    unsigned char* sJj = smem + 64640;

    const int tid  = threadIdx.x;
    const int tile = blockIdx.x;
    const int n    = blockIdx.y;
    const int l0   = tile * TILE_L;
    const int i0   = l0 / 126;

    // load W (flat vectorized copy, padding included)
    {
        const uint4* src = (const uint4*)g_w2;
        uint4* dst = (uint4*)sW;
        for (int t = tid; t < (OD*WSTRIDE*2)/16; t += 256) dst[t] = src[t];
    }
    // load merged tile: 16 channels x 4 rows x 128, rows clamped at 127
    {
        for (int t = tid; t < 64*16; t += 256) {      // 1024 uint4
            int cr = t >> 4;                          // c*4 + r
            int v  = t & 15;
            int c  = cr >> 2, r = cr & 3;
            int grow = i0 + r; if (grow > 127) grow = 127;
            const uint4* src = (const uint4*)(g_pooled + ((n*MCH + c)*HP + grow)*WPD);
            ((uint4*)sM)[cr*16 + v] = src[v];
        }
    }
    if (tid < 128) {
        int l = l0 + tid;
        sDi[tid] = (unsigned char)(l / 126 - i0);
        sJj[tid] = (unsigned char)(l % 126);
        sC[tid]  = g_const2[tid];
    }

    const int warp = tid >> 5, lane = tid & 31;
    const int wm = warp & 3, wn = warp >> 2;       // 4 o-tiles x 2 l-tiles
    const int g = lane >> 2, th = lane & 3;
    const int obase = wm * 32;
    const int lbase = wn * 64;

    float acc[2][8][4];
    #pragma unroll
    for (int mt = 0; mt < 2; mt++)
        #pragma unroll
        for (int nf = 0; nf < 8; nf++)
            #pragma unroll
            for (int q = 0; q < 4; q++) acc[mt][nf][q] = 0.f;

    #pragma unroll
    for (int s = 0; s < 9; s++) {
        const int ki = s / 3, kj = s % 3;
        __syncthreads();    // protect sB from previous iteration's readers
        // stage A-as-B tile: sB[l][c] = merged[c][di(l)+ki][jj(l)+kj]
        for (int t = tid; t < 2048; t += 256) {
            int c = t >> 7, l = t & 127;
            sB[l*18 + c] = sM[(c*4 + sDi[l] + ki)*128 + sJj[l] + kj];
        }
        __syncthreads();

        uint32_t a[2][4];
        #pragma unroll
        for (int mt = 0; mt < 2; mt++) {
            const __nv_bfloat16* ab = &sW[(obase + mt*16 + g)*WSTRIDE + s*16 + th*2];
            a[mt][0] = *(const uint32_t*)(ab);
            a[mt][1] = *(const uint32_t*)(ab + 8*WSTRIDE);
            a[mt][2] = *(const uint32_t*)(ab + 8);
            a[mt][3] = *(const uint32_t*)(ab + 8*WSTRIDE + 8);
        }
        #pragma unroll
        for (int nf = 0; nf < 8; nf++) {
            const __nv_bfloat16* bb = &sB[(lbase + nf*8 + g)*18 + th*2];
            uint32_t b0 = *(const uint32_t*)(bb);
            uint32_t b1 = *(const uint32_t*)(bb + 8);
            mma16816(acc[0][nf], a[0], b0, b1);
            mma16816(acc[1][nf], a[1], b0, b1);
        }
    }

    // epilogue: + const, CELU, masked sum over l, reduce, atomicAdd
    #pragma unroll
    for (int mt = 0; mt < 2; mt++) {
        float cst0 = sC[obase + mt*16 + g];
        float cst1 = sC[obase + mt*16 + g + 8];
        float s0 = 0.f, s1 = 0.f;
        #pragma unroll
        for (int nf = 0; nf < 8; nf++) {
            int lg = l0 + lbase + nf*8 + th*2;
            #pragma unroll
            for (int cc = 0; cc < 2; cc++) {
                if (lg + cc < LTOT) {
                    float v = acc[mt][nf][cc] + cst0;
                    s0 += (v > 0.f) ? v : (__expf(v) - 1.f);
                    float w = acc[mt][nf][2 + cc] + cst1;
                    s1 += (w > 0.f) ? w : (__expf(w) - 1.f);
                }
            }
        }
        #pragma unroll
        for (int off = 1; off < 4; off <<= 1) {
            s0 += __shfl_xor_sync(0xffffffffu, s0, off);
            s1 += __shfl_xor_sync(0xffffffffu, s1, off);
        }
        if (th == 0) {
            atomicAdd(&g_acc[n*OD + obase + mt*16 + g],     s0);
            atomicAdd(&g_acc[n*OD + obase + mt*16 + g + 8], s1);
        }
    }
}

// ---------------- pass 3: mean + clamped L2 normalize ----------------
__global__ void norm_kernel(float* __restrict__ out) {
    int n = blockIdx.x, o = threadIdx.x;
    float a = g_acc[n*OD + o] * (1.f / (float)LTOT);
    float ss = a * a;
    __shared__ float red[4];
    int lane = o & 31, w = o >> 5;
    #pragma unroll
    for (int off = 16; off; off >>= 1) ss += __shfl_xor_sync(0xffffffffu, ss, off);
    if (lane == 0) red[w] = ss;
    __syncthreads();
    float tot = red[0] + red[1] + red[2] + red[3];
    float norm = sqrtf(tot);
    out[n*OD + o] = a / fmaxf(norm, 1e-6f);
}

// ---------------- launch ----------------
extern "C" void kernel_launch(void* const* d_in, const int* in_sizes, int n_in,
                              void* d_out, int out_size) {
    const float* x = (const float*)d_in[0];
    const float* w = (const float*)d_in[1];
    const float* b = (const float*)d_in[2];
    float* out = (float*)d_out;

    prep_kernel<<<1, 256>>>(w, b);
    pool_kernel<<<(NB*MCH*HP*WPD)/256, 256>>>(x);
    cudaFuncSetAttribute(gemm_kernel, cudaFuncAttributeMaxDynamicSharedMemorySize, SMEM_BYTES);
    gemm_kernel<<<dim3(NTILES, NB), 256, SMEM_BYTES>>>();
    norm_kernel<<<NB, 128>>>(out);
}

// round 10
// speedup vs baseline: 1.3541x; 1.3541x over previous
#include <cuda_runtime.h>
#include <cuda_bf16.h>
#include <stdint.h>

#define NB   32
#define MCH  16
#define HP   128
#define WPD  128
#define LTOT (126*126)      // 15876
#define OD   128
#define PD   144
#define CENTER 2.7416f      // E[chi_8]: analytic mean of pooled values

#define TILE_L 128
#define TILES_PER_N 125
#define NTILES (NB*TILES_PER_N)   // 4000
#define GRID_GEMM 296             // 2 CTAs/SM persistent

#define WS 152                    // smem row stride (halves); 304B = 19*16B -> conflict-free ldmatrix
#define W_BYTES (OD*WS*2)         // 38912
#define B_BYTES (TILE_L*WS*2)     // 38912
#define SMEM_BYTES (W_BYTES + B_BYTES)

// ---- static device scratch (no allocation) ----
__device__ __align__(32) __nv_bfloat16 g_pooled[NB*HP*WPD*MCH];  // channel-last, centered bf16
__device__ float g_const2[OD];   // b + CENTER * sum_k W
__device__ float g_acc[NB*OD];

// ---- helpers ----
__device__ __forceinline__ uint32_t smem_u32(const void* p) {
    uint32_t a;
    asm("{ .reg .u64 t; cvta.to.shared.u64 t, %1; cvt.u32.u64 %0, t; }" : "=r"(a) : "l"(p));
    return a;
}
__device__ __forceinline__ void ldsm_x4(uint32_t* r, uint32_t addr) {
    asm volatile("ldmatrix.sync.aligned.m8n8.x4.shared.b16 {%0,%1,%2,%3}, [%4];"
        : "=r"(r[0]), "=r"(r[1]), "=r"(r[2]), "=r"(r[3]) : "r"(addr));
}
__device__ __forceinline__ void mma16816(float* c, const uint32_t* a, uint32_t b0, uint32_t b1) {
    asm volatile(
        "mma.sync.aligned.m16n8k16.row.col.f32.bf16.bf16.f32 "
        "{%0,%1,%2,%3}, {%4,%5,%6,%7}, {%8,%9}, {%0,%1,%2,%3};\n"
        : "+f"(c[0]), "+f"(c[1]), "+f"(c[2]), "+f"(c[3])
        : "r"(a[0]), "r"(a[1]), "r"(a[2]), "r"(a[3]), "r"(b0), "r"(b1));
}

// ---- prep: fold bias + zero accumulators ----
__global__ void prep_kernel(const float* __restrict__ w, const float* __restrict__ b) {
    int tid = threadIdx.x;
    for (int i = tid; i < NB*OD; i += blockDim.x) g_acc[i] = 0.f;
    if (tid < OD) {
        float s = 0.f;
        #pragma unroll 4
        for (int k = 0; k < PD; k++) s += w[tid*PD + k];
        g_const2[tid] = b[tid] + CENTER * s;
    }
}

// ---- pass 1: LPPool3d + center + bf16, channel-last output via smem transpose ----
__global__ void pool_kernel(const float* __restrict__ x) {
    __shared__ __nv_bfloat16 s[128*18];   // [w][mc], stride 18 for bank spread
    int n = blockIdx.x >> 7;
    int h = blockIdx.x & 127;
    int t = threadIdx.x;
    int w = t & 127, mh = t >> 7;
    #pragma unroll
    for (int q = 0; q < 8; q++) {
        int mc = q*2 + mh;
        int dp = mc >> 3, c = mc & 7;
        const float* base = x + ((((n*8 + c)*4 + 2*dp) * 256 + 2*h) * 256 + 2*w);
        float sacc = 0.f;
        #pragma unroll
        for (int dd = 0; dd < 2; dd++)
            #pragma unroll
            for (int hh = 0; hh < 2; hh++) {
                float2 v = *(const float2*)(base + dd*65536 + hh*256);
                sacc += v.x*v.x + v.y*v.y;
            }
        s[w*18 + mc] = __float2bfloat16(sqrtf(sacc) - CENTER);
    }
    __syncthreads();
    int wo = t >> 1, g = (t & 1) * 8;
    uint4 out;
    out.x = *(const uint32_t*)&s[wo*18 + g + 0];
    out.y = *(const uint32_t*)&s[wo*18 + g + 2];
    out.z = *(const uint32_t*)&s[wo*18 + g + 4];
    out.w = *(const uint32_t*)&s[wo*18 + g + 6];
    *(uint4*)(g_pooled + ((n*HP + h)*WPD + wo)*MCH + g) = out;
}

// ---- pass 2: persistent mma.sync implicit-conv GEMM + CELU + sum ----
__global__ __launch_bounds__(256, 2) void gemm_kernel(const float* __restrict__ w) {
    extern __shared__ __align__(16) unsigned char smem[];
    __nv_bfloat16* sW = (__nv_bfloat16*)smem;
    unsigned char*  pB = smem + W_BYTES;
    uint32_t aW = smem_u32(smem);
    uint32_t aB = aW + W_BYTES;

    const int tid = threadIdx.x, warp = tid >> 5, lane = tid & 31;

    // stage W once: column k' = shift*16 + channel (matches B layout)
    for (int t = tid; t < OD*PD; t += 256) {
        int o = t / PD, kp = t - o*PD;
        int sft = kp >> 4, c = kp & 15;
        sW[o*WS + kp] = __float2bfloat16(w[o*PD + c*9 + sft]);
    }

    const int wm = warp & 3, wn = warp >> 2;   // 4 o-tiles x 2 l-halves
    const int g  = lane >> 2, th = lane & 3;
    const int obase = wm * 32;
    const int lbase = wn * 64;

    // per-thread constants (fixed across tiles)
    float cst[2][2];
    #pragma unroll
    for (int mt = 0; mt < 2; mt++) {
        cst[mt][0] = g_const2[obase + mt*16 + g];
        cst[mt][1] = g_const2[obase + mt*16 + g + 8];
    }

    // ldmatrix base addresses
    // A (W): x4 over 16 rows x 16 k: row = obase+mt*16+(lane&15), k-half = (lane>>4)*8
    uint32_t aA[2];
    #pragma unroll
    for (int mt = 0; mt < 2; mt++)
        aA[mt] = aW + (obase + mt*16 + (lane & 15)) * (WS*2) + (lane >> 4) * 16;
    // B: x4 over two 8-row n-tiles x 16 k: row = lbase+p*16+(lane&7)+((lane>>4)<<3),
    //    k-half = ((lane>>3)&1)*8
    uint32_t aBf[4];
    #pragma unroll
    for (int p = 0; p < 4; p++)
        aBf[p] = aB + (lbase + p*16 + (lane & 7) + ((lane >> 4) << 3)) * (WS*2)
                    + ((lane >> 3) & 1) * 16;

    __syncthreads();  // W staged

    for (int idx = blockIdx.x; idx < NTILES; idx += GRID_GEMM) {
        int n = idx / TILES_PER_N;
        int tile = idx - n*TILES_PER_N;
        int l0 = tile * TILE_L;

        // stage B once: sB[l][sft*16+c], 32B per (l,sft), fully vectorized
        for (int t = tid; t < 2304; t += 256) {
            int l = t / 18;
            int r = t - l*18;
            int sft = r >> 1, hf = r & 1;
            int lg = l0 + l; if (lg >= LTOT) lg = LTOT - 1;
            int pi = lg / 126, pj = lg - pi*126;
            int ki = sft / 3, kj = sft - 3*ki;
            const uint4* src = (const uint4*)(g_pooled +
                ((n*HP + pi + ki)*WPD + pj + kj)*MCH + hf*8);
            *(uint4*)(pB + l*(WS*2) + sft*32 + hf*16) = *src;
        }
        __syncthreads();

        float acc[2][8][4];
        #pragma unroll
        for (int mt = 0; mt < 2; mt++)
            #pragma unroll
            for (int nf = 0; nf < 8; nf++)
                #pragma unroll
                for (int q = 0; q < 4; q++) acc[mt][nf][q] = 0.f;

        #pragma unroll
        for (int s = 0; s < 9; s++) {
            uint32_t a0[4], a1[4];
            ldsm_x4(a0, aA[0] + s*32);
            ldsm_x4(a1, aA[1] + s*32);
            #pragma unroll
            for (int p = 0; p < 4; p++) {
                uint32_t bb[4];
                ldsm_x4(bb, aBf[p] + s*32);
                mma16816(acc[0][2*p],   a0, bb[0], bb[1]);
                mma16816(acc[0][2*p+1], a0, bb[2], bb[3]);
                mma16816(acc[1][2*p],   a1, bb[0], bb[1]);
                mma16816(acc[1][2*p+1], a1, bb[2], bb[3]);
            }
        }

        // epilogue: + const, CELU, masked sum over l, quad-reduce, atomicAdd
        #pragma unroll
        for (int mt = 0; mt < 2; mt++) {
            float s0 = 0.f, s1 = 0.f;
            #pragma unroll
            for (int nf = 0; nf < 8; nf++) {
                int lg = l0 + lbase + nf*8 + th*2;
                #pragma unroll
                for (int cc = 0; cc < 2; cc++) {
                    if (lg + cc < LTOT) {
                        float v = acc[mt][nf][cc] + cst[mt][0];
                        s0 += (v > 0.f) ? v : (__expf(v) - 1.f);
                        float u = acc[mt][nf][2 + cc] + cst[mt][1];
                        s1 += (u > 0.f) ? u : (__expf(u) - 1.f);
                    }
                }
            }
            #pragma unroll
            for (int off = 1; off < 4; off <<= 1) {
                s0 += __shfl_xor_sync(0xffffffffu, s0, off);
                s1 += __shfl_xor_sync(0xffffffffu, s1, off);
            }
            if (th == 0) {
                atomicAdd(&g_acc[n*OD + obase + mt*16 + g],     s0);
                atomicAdd(&g_acc[n*OD + obase + mt*16 + g + 8], s1);
            }
        }
        __syncthreads();  // all warps done reading sB before next staging
    }
}

// ---- pass 3: mean + clamped L2 normalize ----
__global__ void norm_kernel(float* __restrict__ out) {
    int n = blockIdx.x, o = threadIdx.x;
    float a = g_acc[n*OD + o] * (1.f / (float)LTOT);
    float ss = a * a;
    __shared__ float red[4];
    int lane = o & 31, w = o >> 5;
    #pragma unroll
    for (int off = 16; off; off >>= 1) ss += __shfl_xor_sync(0xffffffffu, ss, off);
    if (lane == 0) red[w] = ss;
    __syncthreads();
    float norm = sqrtf(red[0] + red[1] + red[2] + red[3]);
    out[n*OD + o] = a / fmaxf(norm, 1e-6f);
}

// ---- launch ----
extern "C" void kernel_launch(void* const* d_in, const int* in_sizes, int n_in,
                              void* d_out, int out_size) {
    const float* x = (const float*)d_in[0];
    const float* w = (const float*)d_in[1];
    const float* b = (const float*)d_in[2];
    float* out = (float*)d_out;

    prep_kernel<<<1, 256>>>(w, b);
    pool_kernel<<<NB*HP, 256>>>(x);
    cudaFuncSetAttribute(gemm_kernel, cudaFuncAttributeMaxDynamicSharedMemorySize, SMEM_BYTES);
    gemm_kernel<<<GRID_GEMM, 256, SMEM_BYTES>>>(w);
    norm_kernel<<<NB, 128>>>(out);
}